// round 1
// baseline (speedup 1.0000x reference)
#include <cuda_runtime.h>
#include <cstdint>

// Problem constants (fixed by the reference: T=8, x shape [T*32, 128, 32, 32])
#define T_STEPS   8
#define BATCH     32
#define CHANNELS  128
#define HW        1024                      // 32*32
#define N_ELEM    (BATCH*CHANNELS*HW)       // 4,194,304 spatial positions
#define NUM_SLABS (N_ELEM/HW)               // 4096 = one (b,c) channel-slab per block

// Scratch (static device globals — no runtime allocation permitted)
__device__ uint8_t g_spikes[N_ELEM];        // 8 spike bits per position, 4 MiB
__device__ float   g_partials[NUM_SLABS];   // per-(b,c)-slab sum of new_thre
__device__ float   g_scale;                 // final scalar thre + update

// ---------------------------------------------------------------------------
// Phase 1: IF recurrence + spike-bit pack + per-slab new_thre partial sums.
// Block = 256 threads * 4 elems = 1024 consecutive n = exactly one (b,c) slab.
// ---------------------------------------------------------------------------
__global__ __launch_bounds__(256) void if_phase1(const float* __restrict__ x,
                                                 const float* __restrict__ thresh) {
    const float thre = __ldg(thresh);
    const int   n    = (blockIdx.x * blockDim.x + threadIdx.x) * 4;

    // Hoist all 8 timestep loads (independent) for MLP=8.
    float4 xv[T_STEPS];
#pragma unroll
    for (int t = 0; t < T_STEPS; t++)
        xv[t] = *reinterpret_cast<const float4*>(x + (size_t)t * N_ELEM + n);

    float    mem[4] = {0.5f * thre, 0.5f * thre, 0.5f * thre, 0.5f * thre};
    unsigned sb[4]  = {0u, 0u, 0u, 0u};
    int      cnt[4] = {0, 0, 0, 0};

#pragma unroll
    for (int t = 0; t < T_STEPS; t++) {
        const float v[4] = {xv[t].x, xv[t].y, xv[t].z, xv[t].w};
#pragma unroll
        for (int j = 0; j < 4; j++) {
            mem[j] += v[j];
            if (mem[j] - thre >= 0.0f) {   // heaviside(mem - cur)
                mem[j] -= thre;            // mem -= s*cur
                sb[j]  |= (1u << t);
                cnt[j]++;
            }
        }
    }

    // Compensation pass -> per-element new_thre, accumulated locally.
    float local = 0.0f;
#pragma unroll
    for (int j = 0; j < 4; j++) {
        const float compen_mem = mem[j] - 0.5f * thre;
        const float cv = fminf(compen_mem + (float)cnt[j] * thre, (float)T_STEPS * thre);
        if (cv > 0.0f && cnt[j] > 0)
            local += cv / (float)cnt[j];
    }

    *reinterpret_cast<uchar4*>(g_spikes + n) =
        make_uchar4((unsigned char)sb[0], (unsigned char)sb[1],
                    (unsigned char)sb[2], (unsigned char)sb[3]);

    // Deterministic block reduction (fixed tree order, no float atomics).
    __shared__ float red[256];
    red[threadIdx.x] = local;
    __syncthreads();
#pragma unroll
    for (int s = 128; s > 0; s >>= 1) {
        if (threadIdx.x < s) red[threadIdx.x] += red[threadIdx.x + s];
        __syncthreads();
    }
    if (threadIdx.x == 0) g_partials[blockIdx.x] = red[0];
}

// ---------------------------------------------------------------------------
// Phase 2: per-channel ub, masked mean over channels -> scalar scale.
// One block, 128 threads (thread c = channel c). Fully deterministic.
// ---------------------------------------------------------------------------
__global__ __launch_bounds__(128) void if_phase2(const float* __restrict__ thresh) {
    const float thre = __ldg(thresh);
    const int   c    = threadIdx.x;

    float s = 0.0f;
#pragma unroll
    for (int b = 0; b < BATCH; b++)          // slab index = b*CHANNELS + c
        s += g_partials[b * CHANNELS + c];
    const float ub      = s / (float)(BATCH * HW);     // mean over (B,H,W)
    const float contrib = (thre > ub) ? (ub - thre) : 0.0f;  // diff * mask

    __shared__ float red[128];
    red[c] = contrib;
    __syncthreads();
#pragma unroll
    for (int st = 64; st > 0; st >>= 1) {
        if (c < st) red[c] += red[c + st];
        __syncthreads();
    }
    if (c == 0)
        g_scale = thre + 0.2f * red[0] / (float)CHANNELS;   // LR*2 = 0.2; mean over C
}

// ---------------------------------------------------------------------------
// Phase 3: expand spike bits * scalar scale to the full [T*B,C,H,W] output.
// Each thread: one uchar4 read, 8 coalesced float4 stores (one per timestep).
// ---------------------------------------------------------------------------
__global__ __launch_bounds__(256) void if_phase3(float* __restrict__ out) {
    const int   n     = (blockIdx.x * blockDim.x + threadIdx.x) * 4;
    const uchar4 sb   = *reinterpret_cast<const uchar4*>(g_spikes + n);
    const float scale = g_scale;

#pragma unroll
    for (int t = 0; t < T_STEPS; t++) {
        float4 o;
        o.x = ((sb.x >> t) & 1) ? scale : 0.0f;
        o.y = ((sb.y >> t) & 1) ? scale : 0.0f;
        o.z = ((sb.z >> t) & 1) ? scale : 0.0f;
        o.w = ((sb.w >> t) & 1) ? scale : 0.0f;
        *reinterpret_cast<float4*>(out + (size_t)t * N_ELEM + n) = o;
    }
}

// ---------------------------------------------------------------------------
extern "C" void kernel_launch(void* const* d_in, const int* in_sizes, int n_in,
                              void* d_out, int out_size) {
    const float* x      = (const float*)d_in[0];   // [T*B, C, H, W] fp32
    const float* thresh = (const float*)d_in[1];   // [1] fp32
    float*       out    = (float*)d_out;

    if_phase1<<<NUM_SLABS, 256>>>(x, thresh);      // 4096 blocks
    if_phase2<<<1, 128>>>(thresh);
    if_phase3<<<N_ELEM / (256 * 4), 256>>>(out);   // 4096 blocks
}